// round 4
// baseline (speedup 1.0000x reference)
#include <cuda_runtime.h>
#include <cuda_bf16.h>

// ---------------------------------------------------------------------------
// 2-layer GCN + linear classifier.
//   h1 = relu(Agg(x @ W1) + b1); h2 = relu(Agg(h1 @ W2) + b2); out = h2 @ Wc + bc
// Agg(t)[n] = t[n]*inv[n]^2 + sum_{e: dst=n} t[src_e]*inv[src_e]*inv[n]
// inv[i] = rsqrt(1 + #edges with dst==i)   (self-loops included)
// ---------------------------------------------------------------------------

#define MAXN 50176
#define MAXE 1200000
#define DIN 64

__device__ int   g_deg[MAXN];
__device__ float g_inv[MAXN];
__device__ int   g_off[MAXN];
__device__ int   g_cur[MAXN];
__device__ int   g_bsum[1024];
__device__ int   g_csrc[MAXE];
__device__ float g_wgt[MAXE];
__device__ float g_A[MAXN * DIN];
__device__ float g_B[MAXN * DIN];
__device__ int   g_is64;

// --------------------------- index width handling --------------------------

__global__ void detect64_k(const int* __restrict__ w) {
    // If the edge buffer is int64 (values < 2^31), every odd 32-bit word is 0.
    int ok = 1;
    for (int i = 1; i < 256; i += 2)
        if (w[i] != 0) { ok = 0; break; }
    g_is64 = ok;
}

__device__ __forceinline__ int load_idx(const void* p, long i, int is64) {
    if (is64) return (int)((const long long*)p)[i];
    return ((const int*)p)[i];
}

// ------------------------------- CSR build ---------------------------------

__global__ void init_deg_k(int n) {
    int i = blockIdx.x * blockDim.x + threadIdx.x;
    if (i < n) g_deg[i] = 1;  // self loop
}

__global__ void count_deg_k(const void* __restrict__ ei, int E) {
    int e = blockIdx.x * blockDim.x + threadIdx.x;
    if (e >= E) return;
    int is64 = g_is64;
    int d = load_idx(ei, (long)E + e, is64);
    atomicAdd(&g_deg[d], 1);
}

__global__ void inv_k(int n) {
    int i = blockIdx.x * blockDim.x + threadIdx.x;
    if (i < n) g_inv[i] = rsqrtf((float)g_deg[i]);
}

__global__ void scan1_k(int n) {
    __shared__ int s[1024];
    int i = blockIdx.x * 1024 + threadIdx.x;
    int v = (i < n) ? (g_deg[i] - 1) : 0;
    s[threadIdx.x] = v;
    __syncthreads();
    #pragma unroll
    for (int d = 1; d < 1024; d <<= 1) {
        int t = (threadIdx.x >= d) ? s[threadIdx.x - d] : 0;
        __syncthreads();
        s[threadIdx.x] += t;
        __syncthreads();
    }
    if (i < n) g_off[i] = s[threadIdx.x];       // inclusive scan (temp)
    if (threadIdx.x == 1023) g_bsum[blockIdx.x] = s[1023];
}

__global__ void scan2_k(int nb) {
    if (threadIdx.x == 0 && blockIdx.x == 0) {
        int run = 0;
        for (int b = 0; b < nb; b++) {
            int t = g_bsum[b];
            g_bsum[b] = run;
            run += t;
        }
    }
}

__global__ void scan3_k(int n) {
    int i = blockIdx.x * 1024 + threadIdx.x;
    if (i >= n) return;
    int c = g_deg[i] - 1;
    int excl = g_off[i] - c + g_bsum[blockIdx.x];
    g_off[i] = excl;
    g_cur[i] = excl;
}

__global__ void scatter_k(const void* __restrict__ ei, int E) {
    int e = blockIdx.x * blockDim.x + threadIdx.x;
    if (e >= E) return;
    int is64 = g_is64;
    int s = load_idx(ei, e, is64);
    int d = load_idx(ei, (long)E + e, is64);
    int pos = atomicAdd(&g_cur[d], 1);
    g_csrc[pos] = s;
    g_wgt[pos]  = g_inv[s] * g_inv[d];
}

// --------------------------------- GEMM ------------------------------------
// Y[n, FOUT] = X[n, 64] @ W[64, FOUT] (+ bias).  block = (FOUT/4, BY)

template <int FOUT, int BY>
__global__ __launch_bounds__(FOUT / 4 * BY) void gemm_k(
    const float* __restrict__ X, const float* __restrict__ W,
    const float* __restrict__ bias, float* __restrict__ Y, int n) {
    constexpr int TX = FOUT / 4;
    __shared__ __align__(16) float Ws[DIN * FOUT];
    __shared__ float Xs[BY][DIN + 1];

    int tid = threadIdx.y * TX + threadIdx.x;
    constexpr int NTH = TX * BY;
    for (int i = tid; i < DIN * FOUT; i += NTH) Ws[i] = W[i];

    int rb = blockIdx.x * BY;
    for (int i = tid; i < BY * DIN; i += NTH) {
        int r = i / DIN, c = i % DIN;
        Xs[r][c] = (rb + r < n) ? X[(long)(rb + r) * DIN + c] : 0.0f;
    }
    __syncthreads();

    int row = rb + threadIdx.y;
    float4 acc = make_float4(0.f, 0.f, 0.f, 0.f);
    #pragma unroll
    for (int k = 0; k < DIN; k++) {
        float xv = Xs[threadIdx.y][k];
        float4 w = *(const float4*)&Ws[k * FOUT + threadIdx.x * 4];
        acc.x = fmaf(xv, w.x, acc.x);
        acc.y = fmaf(xv, w.y, acc.y);
        acc.z = fmaf(xv, w.z, acc.z);
        acc.w = fmaf(xv, w.w, acc.w);
    }
    if (row < n) {
        if (bias) {
            float4 b = *(const float4*)&bias[threadIdx.x * 4];
            acc.x += b.x; acc.y += b.y; acc.z += b.z; acc.w += b.w;
        }
        *(float4*)&Y[(long)row * FOUT + threadIdx.x * 4] = acc;
    }
}

// ------------------------------ aggregation --------------------------------
// One warp per node; each lane owns 2 feature channels (float2).

__global__ __launch_bounds__(256) void aggregate_k(
    const float* __restrict__ T, const float* __restrict__ bias,
    float* __restrict__ H, int n) {
    int warp = (blockIdx.x * blockDim.x + threadIdx.x) >> 5;
    int lane = threadIdx.x & 31;
    if (warp >= n) return;
    int node = warp;

    const float2* Tv = (const float2*)T;
    float invn = g_inv[node];
    float w0 = invn * invn;
    float2 sv = Tv[(long)node * 32 + lane];
    float accx = sv.x * w0, accy = sv.y * w0;

    int start = g_off[node];
    int cnt = g_deg[node] - 1;

    for (int base = 0; base < cnt; base += 32) {
        int j = base + lane;
        int s   = (j < cnt) ? g_csrc[start + j] : 0;
        float wv = (j < cnt) ? g_wgt[start + j] : 0.0f;
        int rem = cnt - base;
        int m = rem < 32 ? rem : 32;
        #pragma unroll 4
        for (int k = 0; k < m; k++) {
            int ss   = __shfl_sync(0xffffffffu, s, k);
            float ww = __shfl_sync(0xffffffffu, wv, k);
            float2 hv = Tv[(long)ss * 32 + lane];
            accx = fmaf(hv.x, ww, accx);
            accy = fmaf(hv.y, ww, accy);
        }
    }

    float2 b = ((const float2*)bias)[lane];
    accx = fmaxf(accx + b.x, 0.0f);
    accy = fmaxf(accy + b.y, 0.0f);
    ((float2*)H)[(long)node * 32 + lane] = make_float2(accx, accy);
}

// --------------------------------- launch ----------------------------------

extern "C" void kernel_launch(void* const* d_in, const int* in_sizes, int n_in,
                              void* d_out, int out_size) {
    const float* x  = (const float*)d_in[0];
    const void*  ei = d_in[1];
    const float* W1 = (const float*)d_in[2];
    const float* b1 = (const float*)d_in[3];
    const float* W2 = (const float*)d_in[4];
    const float* b2 = (const float*)d_in[5];
    const float* Wc = (const float*)d_in[6];
    const float* bc = (const float*)d_in[7];
    float* out = (float*)d_out;

    int n = in_sizes[0] / DIN;       // 50000
    int E = in_sizes[1] / 2;         // 800000

    float *A, *B;
    cudaGetSymbolAddress((void**)&A, g_A);
    cudaGetSymbolAddress((void**)&B, g_B);

    int tN = (n + 255) / 256;
    int tE = (E + 255) / 256;
    int nb = (n + 1023) / 1024;

    detect64_k<<<1, 1>>>((const int*)ei);
    init_deg_k<<<tN, 256>>>(n);
    count_deg_k<<<tE, 256>>>(ei, E);
    inv_k<<<tN, 256>>>(n);
    scan1_k<<<nb, 1024>>>(n);
    scan2_k<<<1, 32>>>(nb);
    scan3_k<<<nb, 1024>>>(n);
    scatter_k<<<tE, 256>>>(ei, E);

    dim3 gblk(16, 16);                       // FOUT=64
    int ggrid = (n + 15) / 16;
    int agrid = (n + 7) / 8;                 // 8 warps / block

    gemm_k<64, 16><<<ggrid, gblk>>>(x, W1, nullptr, A, n);
    aggregate_k<<<agrid, 256>>>(A, b1, B, n);
    gemm_k<64, 16><<<ggrid, gblk>>>(B, W2, nullptr, A, n);
    aggregate_k<<<agrid, 256>>>(A, b2, B, n);

    dim3 cblk(4, 64);                        // FOUT=16
    gemm_k<16, 64><<<(n + 63) / 64, cblk>>>(B, Wc, bc, out, n);
}

// round 6
// speedup vs baseline: 1.1217x; 1.1217x over previous
#include <cuda_runtime.h>
#include <cuda_bf16.h>

// ---------------------------------------------------------------------------
// 2-layer GCN + linear classifier.
//   h1 = relu(Agg(x @ W1) + b1); h2 = relu(Agg(h1 @ W2) + b2); out = h2 @ Wc + bc
// Agg(t)[n] = t[n]*inv[n]^2 + sum_{e: dst=n} t[src_e]*inv[src_e]*inv[n]
// inv[i] = rsqrt(1 + #edges with dst==i)
//
// R4/R5: parallel is64-detect, warp-parallel block-sum scan, inv fused into
//     scan1, packed (src,wgt) edge records, GEMM2 fused into agg1 epilogue,
//     classifier fused into agg2 epilogue. 13 launches -> 9.
//     (R5 = R4 resubmit after infra failure, + __ldg on CSR metadata.)
// ---------------------------------------------------------------------------

#define MAXN 50176
#define MAXE 1200000
#define DIN 64

__device__ int   g_deg[MAXN];
__device__ float g_inv[MAXN];
__device__ int   g_off[MAXN];
__device__ int   g_cur[MAXN];
__device__ int   g_bsum[1024];
__device__ int2  g_edge[MAXE];     // {src, float-bits weight}
__device__ float g_A[MAXN * DIN];
__device__ float g_B[MAXN * DIN];
__device__ int   g_is64;

// --------------------------- index width handling --------------------------

__device__ __forceinline__ int load_idx(const void* p, long i, int is64) {
    if (is64) return (int)((const long long*)p)[i];
    return ((const int*)p)[i];
}

// init deg=1 everywhere; block 0 / warp 0 detects index width in parallel
// (if the buffer is int64 with values < 2^31, every odd 32-bit word is 0).
__global__ void init_k(const int* __restrict__ w, int n) {
    int i = blockIdx.x * blockDim.x + threadIdx.x;
    if (i < n) g_deg[i] = 1;
    if (blockIdx.x == 0 && threadIdx.x < 32) {
        int bad = 0;
        #pragma unroll
        for (int j = 0; j < 4; j++) {
            int idx = 1 + 2 * (threadIdx.x * 4 + j);   // odd words 1..255
            if (w[idx] != 0) bad = 1;
        }
        unsigned m = __ballot_sync(0xffffffffu, bad);
        if (threadIdx.x == 0) g_is64 = (m == 0u);
    }
}

// ------------------------------- CSR build ---------------------------------

__global__ void count_deg_k(const void* __restrict__ ei, int E) {
    int e = blockIdx.x * blockDim.x + threadIdx.x;
    if (e >= E) return;
    int is64 = g_is64;
    int d = load_idx(ei, (long)E + e, is64);
    atomicAdd(&g_deg[d], 1);
}

// block-local inclusive scan of (deg-1); also finalizes g_inv.
__global__ void scan1_k(int n) {
    __shared__ int s[1024];
    int i = blockIdx.x * 1024 + threadIdx.x;
    int v = (i < n) ? (g_deg[i] - 1) : 0;
    if (i < n) g_inv[i] = rsqrtf((float)(v + 1));
    s[threadIdx.x] = v;
    __syncthreads();
    #pragma unroll
    for (int d = 1; d < 1024; d <<= 1) {
        int t = (threadIdx.x >= d) ? s[threadIdx.x - d] : 0;
        __syncthreads();
        s[threadIdx.x] += t;
        __syncthreads();
    }
    if (i < n) g_off[i] = s[threadIdx.x];
    if (threadIdx.x == 1023) g_bsum[blockIdx.x] = s[1023];
}

// warp-parallel exclusive scan of up to 64 block sums (nb = 49 here).
__global__ void scan2_k(int nb) {
    int lane = threadIdx.x;                     // 32 threads
    int v0 = (lane < nb)      ? g_bsum[lane]      : 0;
    int v1 = (lane + 32 < nb) ? g_bsum[lane + 32] : 0;
    int s0 = v0, s1 = v1;
    #pragma unroll
    for (int d = 1; d < 32; d <<= 1) {
        int t0 = __shfl_up_sync(0xffffffffu, s0, d);
        int t1 = __shfl_up_sync(0xffffffffu, s1, d);
        if (lane >= d) { s0 += t0; s1 += t1; }
    }
    int tot0 = __shfl_sync(0xffffffffu, s0, 31);
    s1 += tot0;
    if (lane < nb)      g_bsum[lane]      = s0 - v0;   // exclusive
    if (lane + 32 < nb) g_bsum[lane + 32] = s1 - v1;
}

__global__ void scan3_k(int n) {
    int i = blockIdx.x * 1024 + threadIdx.x;
    if (i >= n) return;
    int c = g_deg[i] - 1;
    int excl = g_off[i] - c + g_bsum[blockIdx.x];
    g_off[i] = excl;
    g_cur[i] = excl;
}

__global__ void scatter_k(const void* __restrict__ ei, int E) {
    int e = blockIdx.x * blockDim.x + threadIdx.x;
    if (e >= E) return;
    int is64 = g_is64;
    int s = load_idx(ei, e, is64);
    int d = load_idx(ei, (long)E + e, is64);
    int pos = atomicAdd(&g_cur[d], 1);
    g_edge[pos] = make_int2(s, __float_as_int(g_inv[s] * g_inv[d]));
}

// --------------------------------- GEMM1 -----------------------------------
// Y[n,64] = X[n,64] @ W[64,64]. block = (16, 16)

__global__ __launch_bounds__(256) void gemm_k(
    const float* __restrict__ X, const float* __restrict__ W,
    float* __restrict__ Y, int n) {
    __shared__ __align__(16) float Ws[DIN * DIN];
    __shared__ float Xs[16][DIN + 1];

    int tid = threadIdx.y * 16 + threadIdx.x;
    for (int i = tid; i < DIN * DIN; i += 256) Ws[i] = W[i];

    int rb = blockIdx.x * 16;
    for (int i = tid; i < 16 * DIN; i += 256) {
        int r = i / DIN, c = i % DIN;
        Xs[r][c] = (rb + r < n) ? X[(long)(rb + r) * DIN + c] : 0.0f;
    }
    __syncthreads();

    int row = rb + threadIdx.y;
    float4 acc = make_float4(0.f, 0.f, 0.f, 0.f);
    #pragma unroll
    for (int k = 0; k < DIN; k++) {
        float xv = Xs[threadIdx.y][k];
        float4 w = *(const float4*)&Ws[k * DIN + threadIdx.x * 4];
        acc.x = fmaf(xv, w.x, acc.x);
        acc.y = fmaf(xv, w.y, acc.y);
        acc.z = fmaf(xv, w.z, acc.z);
        acc.w = fmaf(xv, w.w, acc.w);
    }
    if (row < n)
        *(float4*)&Y[(long)row * DIN + threadIdx.x * 4] = acc;
}

// ---------------------- aggregation + fused epilogue ------------------------
// One warp per node, lane owns 2 feature channels. After aggregation
// (+bias+relu), the warp immediately multiplies its h-row by W (in smem):
//   FOUT=64 : t2 = h @ W2               -> Y[node,64]
//   FOUT=16 : out = h @ Wc + bias2      -> Y[node,16]

template <int FOUT>
__global__ __launch_bounds__(256) void agg_mm_k(
    const float* __restrict__ T, const float* __restrict__ bias,
    const float* __restrict__ W, const float* __restrict__ bias2,
    float* __restrict__ Y, int n) {
    __shared__ __align__(16) float Ws[DIN * FOUT];
    __shared__ __align__(16) float hbuf[8][DIN];
    __shared__ __align__(16) int2  ebuf[8][32];

    int tid  = threadIdx.x;
    int wrp  = tid >> 5;
    int lane = tid & 31;

    for (int i = tid; i < DIN * FOUT; i += 256) Ws[i] = W[i];
    __syncthreads();

    int node = blockIdx.x * 8 + wrp;
    if (node >= n) return;

    const float2* Tv = (const float2*)T;
    float invn = __ldg(&g_inv[node]);
    float w0 = invn * invn;
    float2 sv = Tv[(long)node * 32 + lane];
    float accx = sv.x * w0, accy = sv.y * w0;

    int start = __ldg(&g_off[node]);
    int cnt = __ldg(&g_deg[node]) - 1;

    for (int base = 0; base < cnt; base += 32) {
        int j = base + lane;
        int2 ev = (j < cnt) ? g_edge[start + j] : make_int2(0, 0);
        ebuf[wrp][lane] = ev;
        __syncwarp();
        int m = cnt - base; if (m > 32) m = 32;
        #pragma unroll 4
        for (int k = 0; k < m; k++) {
            int2 e = ebuf[wrp][k];
            float ww = __int_as_float(e.y);
            float2 hv = Tv[(long)e.x * 32 + lane];
            accx = fmaf(hv.x, ww, accx);
            accy = fmaf(hv.y, ww, accy);
        }
        __syncwarp();
    }

    float2 b = ((const float2*)bias)[lane];
    accx = fmaxf(accx + b.x, 0.0f);
    accy = fmaxf(accy + b.y, 0.0f);
    *(float2*)&hbuf[wrp][2 * lane] = make_float2(accx, accy);
    __syncwarp();

    if (FOUT == 64) {
        float ox = 0.f, oy = 0.f;
        #pragma unroll
        for (int k = 0; k < DIN; k++) {
            float hk = hbuf[wrp][k];
            float2 wv = *(const float2*)&Ws[k * 64 + 2 * lane];
            ox = fmaf(hk, wv.x, ox);
            oy = fmaf(hk, wv.y, oy);
        }
        ((float2*)Y)[(long)node * 32 + lane] = make_float2(ox, oy);
    } else {
        // 16 outputs: lane -> output (lane&15), k-half (lane>>4), then pair-reduce
        int o = lane & 15;
        int k0 = (lane >> 4) * 32;
        float acc = 0.f;
        #pragma unroll
        for (int k = 0; k < 32; k++) {
            float hk = hbuf[wrp][k0 + k];
            acc = fmaf(hk, Ws[(k0 + k) * FOUT + o], acc);
        }
        acc += __shfl_down_sync(0xffffffffu, acc, 16);
        if (lane < 16)
            Y[(long)node * FOUT + o] = acc + bias2[o];
    }
}

// --------------------------------- launch ----------------------------------

extern "C" void kernel_launch(void* const* d_in, const int* in_sizes, int n_in,
                              void* d_out, int out_size) {
    const float* x  = (const float*)d_in[0];
    const void*  ei = d_in[1];
    const float* W1 = (const float*)d_in[2];
    const float* b1 = (const float*)d_in[3];
    const float* W2 = (const float*)d_in[4];
    const float* b2 = (const float*)d_in[5];
    const float* Wc = (const float*)d_in[6];
    const float* bc = (const float*)d_in[7];
    float* out = (float*)d_out;

    int n = in_sizes[0] / DIN;       // 50000
    int E = in_sizes[1] / 2;         // 800000

    float *A, *B;
    cudaGetSymbolAddress((void**)&A, g_A);
    cudaGetSymbolAddress((void**)&B, g_B);

    int tN = (n + 255) / 256;
    int tE = (E + 255) / 256;
    int nb = (n + 1023) / 1024;
    int agrid = (n + 7) / 8;

    init_k<<<tN, 256>>>((const int*)ei, n);
    count_deg_k<<<tE, 256>>>(ei, E);
    scan1_k<<<nb, 1024>>>(n);
    scan2_k<<<1, 32>>>(nb);
    scan3_k<<<nb, 1024>>>(n);
    scatter_k<<<tE, 256>>>(ei, E);

    gemm_k<<<(n + 15) / 16, dim3(16, 16)>>>(x, W1, A, n);        // A = x @ W1
    agg_mm_k<64><<<agrid, 256>>>(A, b1, W2, nullptr, B, n);      // B = relu(Agg A + b1) @ W2
    agg_mm_k<16><<<agrid, 256>>>(B, b2, Wc, bc, out, n);         // out = relu(Agg B + b2) @ Wc + bc
}